// round 9
// baseline (speedup 1.0000x reference)
#include <cuda_runtime.h>
#include <cuda_bf16.h>

// ---------------------------------------------------------------------------
// TPoseHuman fused 6-part MLP — layers 2 AND 3 on mma.sync bf16 (3-chain
// hi/lo error compensation). 2 CTAs/SM (112KB smem).
// R9: pair-local weight streaming. Each warp-pair (2 warps sharing an n-slice)
// fetches only its 4KB quarter of every 16KB stage and syncs with a pair-
// scoped named barrier (bar.sync id,64). CTA-wide __syncthreads only at
// layer1 / h2-epilogue / W3 stages -> 5 CTA barriers per part instead of 19.
// ---------------------------------------------------------------------------

#define NPTS    65536
#define PPARTS  6
#define TM      64
#define NCTAS   (NPTS / TM)       // 1024
#define THREADS 256
#define OUTC    27
#define SPP     18                // stages per part: 16 layer2 + 2 layer3
#define NSTG    (PPARTS * SPP)    // 108

// ---- smem byte offsets ----
#define OFF_RING 0u               // 3 x 16384 = 49152
#define OFF_AHI  49152u           // 64 rows x 512B (A hi / h2 hi)
#define OFF_ALO  81920u           // 64 rows x 512B (A lo / h2 lo)
#define SMEM_BYTES 114688         // 112 KB -> 2 CTAs/SM

// ---------------------------------------------------------------------------
// asm helpers (baseline PTX, sm_80-era: family-safe on compute_103)
// ---------------------------------------------------------------------------
__device__ __forceinline__ unsigned smem_to_u32(const void* p) {
    unsigned a;
    asm("{ .reg .u64 t; cvta.to.shared.u64 t, %1; cvt.u32.u64 %0, t; }"
        : "=r"(a) : "l"(p));
    return a;
}
#define LDSM4(r, addr) \
    asm volatile("ldmatrix.sync.aligned.m8n8.x4.shared.b16 {%0,%1,%2,%3}, [%4];" \
        : "=r"((r)[0]), "=r"((r)[1]), "=r"((r)[2]), "=r"((r)[3]) : "r"(addr))
#define MMA16816(d, a, b0r, b1r) \
    asm volatile("mma.sync.aligned.m16n8k16.row.col.f32.bf16.bf16.f32 " \
        "{%0,%1,%2,%3}, {%4,%5,%6,%7}, {%8,%9}, {%0,%1,%2,%3};" \
        : "+f"((d)[0]), "+f"((d)[1]), "+f"((d)[2]), "+f"((d)[3]) \
        : "r"((a)[0]), "r"((a)[1]), "r"((a)[2]), "r"((a)[3]), \
          "r"(b0r), "r"(b1r))
#define PAIR_BAR(id) \
    asm volatile("bar.sync %0, 64;" :: "r"(id) : "memory")
__device__ __forceinline__ unsigned pack_bf16x2(float x, float y) {
    __nv_bfloat162 t = __floats2bfloat162_rn(x, y);
    return *(unsigned*)&t;
}

// ---------------------------------------------------------------------------
// persistent scratch
// ---------------------------------------------------------------------------
// Uniform 16KB stages: per part, stages 0..15 = W2^T k-chunks (hi,lo pairs),
// stages 16,17 = W3img (hi,lo). 64B-row layout, swizzle off ^= ((n>>1)&3)<<4.
__device__ __align__(16) unsigned char g_Bimg[NSTG * 16384];
__device__ __align__(16) float g_W1r  [PPARTS * 9 * 256];
__device__ __align__(16) float g_b1eff[PPARTS * 256];
__device__ __align__(16) float g_b3   [PPARTS * 32];

// ---------------------------------------------------------------------------
// prep kernels
// ---------------------------------------------------------------------------
__global__ void prep_small(const float* __restrict__ W1, const float* __restrict__ b1,
                           const float* __restrict__ b3, const float* __restrict__ bocc,
                           const float* __restrict__ frame) {
    int p = blockIdx.x, d = threadIdx.x;
    const int rows[9] = {0, 1, 2, 11, 12, 13, 14, 15, 16};
    float be = b1[p * 256 + d];
#pragma unroll
    for (int f = 0; f < 8; ++f)
        be += frame[f] * W1[(p * 17 + 3 + f) * 256 + d];
    g_b1eff[p * 256 + d] = be;
#pragma unroll
    for (int i = 0; i < 9; ++i)
        g_W1r[(p * 9 + i) * 256 + d] = W1[(p * 17 + rows[i]) * 256 + d];
    if (d < 32) {
        float v = 0.f;
        if (d < 20)  v = b3[p * 20 + d];
        if (d == 20) v = bocc[p];
        g_b3[p * 32 + d] = v;
    }
}

// layer2 B images: Bs[n][k] = W2[p][k][n], hi/lo bf16, 64B-row swizzled stages
__global__ void prep_B2(const float* __restrict__ W2) {
    int p = blockIdx.x, k = blockIdx.y, n = threadIdx.x;
    float w = W2[((size_t)(p * 256 + k)) * 256 + n];
    __nv_bfloat16 hi = __float2bfloat16(w);
    __nv_bfloat16 lo = __float2bfloat16(w - __bfloat162float(hi));
    int s_hi = (k >> 5) * 2;                       // stage pair for this k-window
    unsigned off = (unsigned)(n * 64 + ((k >> 4) & 1) * 32 + (k & 15) * 2);
    off ^= (unsigned)(((n >> 1) & 3) << 4);
    unsigned char* base = g_Bimg + ((size_t)(p * SPP + s_hi)) * 16384;
    *(__nv_bfloat16*)(base + off)         = hi;
    *(__nv_bfloat16*)(base + 16384 + off) = lo;
}

// layer3 B images: B3[n][k] = [W3|Wocc|0pad]^T, n 0..31, k 0..255
__global__ void prep_B3(const float* __restrict__ W3,
                        const float* __restrict__ Wocc) {
    int p = blockIdx.x, k = blockIdx.y, n = threadIdx.x;   // n < 32
    float w = 0.f;
    if (n < 20)  w = W3[((size_t)(p * 256 + k)) * 20 + n];
    if (n == 20) w = Wocc[p * 256 + k];
    __nv_bfloat16 hi = __float2bfloat16(w);
    __nv_bfloat16 lo = __float2bfloat16(w - __bfloat162float(hi));
    unsigned off = (unsigned)((k >> 5) * 2048 + n * 64 +
                              ((k >> 4) & 1) * 32 + (k & 15) * 2);
    off ^= (unsigned)(((n >> 1) & 3) << 4);
    unsigned char* base = g_Bimg + ((size_t)(p * SPP + 16)) * 16384;
    *(__nv_bfloat16*)(base + off)         = hi;
    *(__nv_bfloat16*)(base + 16384 + off) = lo;
}

// ---------------------------------------------------------------------------
// main fused kernel
// ---------------------------------------------------------------------------
// Per-warp quarter prefetch: pair wx owns bytes [wx*4096, +4096) of every
// stage; warp fetches its wy half (2KB = 64B/lane).
__device__ __forceinline__ void prefetch_quarter(unsigned ring, int wx, int wy,
                                                 int lane, int g) {
    const unsigned qoff = (unsigned)(wx * 4096 + wy * 2048 + lane * 64);
    const unsigned char* src = g_Bimg + (size_t)g * 16384 + qoff;
    unsigned dst = ring + (unsigned)((g % 3) * 16384) + qoff;
#pragma unroll
    for (int j = 0; j < 4; ++j)
        asm volatile("cp.async.cg.shared.global [%0], [%1], 16;"
                     :: "r"(dst + j * 16), "l"(src + j * 16));
    asm volatile("cp.async.commit_group;" ::: "memory");
}

__global__ void __launch_bounds__(THREADS, 2)
fused_kernel(const float* __restrict__ tpts,
             const float* __restrict__ bigpts,
             const float* __restrict__ viewdir,
             const float* __restrict__ b2g,
             const int* __restrict__ tflag,
             float* __restrict__ out) {
    extern __shared__ unsigned char smc[];
    const int tid  = threadIdx.x;
    const int lane = tid & 31;
    const int wid  = tid >> 5;
    const int wy   = wid >> 2;          // layer2: m tile of 32
    const int wx   = wid & 3;           // layer2: n tile of 64 (= pair id)
    const int n0   = blockIdx.x * TM;

    const unsigned sb   = smem_to_u32(smc);
    const unsigned ring = sb + OFF_RING;

    // ---- layer2 ldmatrix bases (validated R6/R7/R8) ----
    unsigned a_rb[2], a_msk[2];
#pragma unroll
    for (int mt = 0; mt < 2; ++mt) {
        int ml = wy * 32 + mt * 16 + (lane & 15);
        a_rb[mt]  = (unsigned)(ml * 512 + (lane >> 4) * 16);
        a_msk[mt] = (unsigned)((ml & 7) << 4);
    }
    unsigned b_off[4], b_sw[4];
#pragma unroll
    for (int t = 0; t < 4; ++t) {
        int n = wx * 64 + t * 16 + (lane & 7) + ((lane & 16) ? 8 : 0);
        b_off[t] = (unsigned)(n * 64 + ((lane & 8) ? 16 : 0));
        b_sw[t]  = (unsigned)(((n >> 1) & 3) << 4);
    }
    // ---- layer3 bases: warp w -> m-tile (w>>1), n-half (w&1) ----
    const int ml3 = (wid >> 1) * 16 + (lane & 15);
    const unsigned a3_rb  = (unsigned)(ml3 * 512 + (lane >> 4) * 16);
    const unsigned a3_msk = (unsigned)((ml3 & 7) << 4);
    const int n3 = (wid & 1) * 16 + (lane & 7) + ((lane & 16) ? 8 : 0);
    const unsigned b3_off = (unsigned)(n3 * 64 + ((lane & 8) ? 16 : 0));
    const unsigned b3_sw  = (unsigned)(((n3 >> 1) & 3) << 4);
    const int r0 = (wid >> 1) * 16 + (lane >> 2);
    const int r1 = r0 + 8;
    const int cbase = (wid & 1) * 16 + (lane & 3) * 2;

    float sums[2][4];
#pragma unroll
    for (int t = 0; t < 2; ++t)
#pragma unroll
        for (int q = 0; q < 4; ++q) sums[t][q] = 0.f;

    prefetch_quarter(ring, wx, wy, lane, 0);

    for (int p = 0; p < PPARTS; ++p) {
        // ---------------- layer 1 (thread = (m, d-chunk of 64)) ----------
        {
            const int m1 = tid & 63;
            const int dc = tid >> 6;
            const int gi = (n0 + m1) * PPARTS + p;
            float x[9];
            x[0] = tpts[gi*3];    x[1] = tpts[gi*3+1];    x[2] = tpts[gi*3+2];
            x[3] = bigpts[gi*3];  x[4] = bigpts[gi*3+1];  x[5] = bigpts[gi*3+2];
            x[6] = viewdir[gi*3]; x[7] = viewdir[gi*3+1]; x[8] = viewdir[gi*3+2];
            const float* w1  = g_W1r + p * 2304;
            const float* b1e = g_b1eff + p * 256;
            const unsigned amask = (unsigned)((m1 & 7) << 4);
            const unsigned mrow  = (unsigned)(m1 * 512 + dc * 128);
#pragma unroll 4
            for (int gq = 0; gq < 16; ++gq) {
                const int d = dc * 64 + gq * 4;
                float4 a = *(const float4*)(b1e + d);
#pragma unroll
                for (int i = 0; i < 9; ++i) {
                    float4 w = *(const float4*)(w1 + i * 256 + d);
                    a.x += x[i]*w.x; a.y += x[i]*w.y;
                    a.z += x[i]*w.z; a.w += x[i]*w.w;
                }
                a.x = fmaxf(a.x, 0.f); a.y = fmaxf(a.y, 0.f);
                a.z = fmaxf(a.z, 0.f); a.w = fmaxf(a.w, 0.f);
                float hx = __bfloat162float(__float2bfloat16(a.x));
                float hy = __bfloat162float(__float2bfloat16(a.y));
                float hz = __bfloat162float(__float2bfloat16(a.z));
                float hw = __bfloat162float(__float2bfloat16(a.w));
                unsigned o0 = (mrow + gq * 8) ^ amask;
                unsigned o1 = (mrow + gq * 8 + 4) ^ amask;
                *(unsigned*)(smc + OFF_AHI + o0) = pack_bf16x2(a.x, a.y);
                *(unsigned*)(smc + OFF_AHI + o1) = pack_bf16x2(a.z, a.w);
                *(unsigned*)(smc + OFF_ALO + o0) = pack_bf16x2(a.x - hx, a.y - hy);
                *(unsigned*)(smc + OFF_ALO + o1) = pack_bf16x2(a.z - hz, a.w - hw);
            }
        }
        __syncthreads();   // (e) A planes ready CTA-wide

        float acc[2][8][4];
#pragma unroll
        for (int mt = 0; mt < 2; ++mt)
#pragma unroll
            for (int nt = 0; nt < 8; ++nt)
#pragma unroll
                for (int q = 0; q < 4; ++q) acc[mt][nt][q] = 0.f;
        float acc3[2][4];
#pragma unroll
        for (int t = 0; t < 2; ++t)
#pragma unroll
            for (int q = 0; q < 4; ++q) acc3[t][q] = 0.f;

#pragma unroll 1
        for (int s = 0; s < SPP; ++s) {
            const int g = p * SPP + s;
            // per-warp depth-1 quarter prefetch into 3-slot ring
            if (g + 1 < NSTG) {
                prefetch_quarter(ring, wx, wy, lane, g + 1);
                asm volatile("cp.async.wait_group 1;" ::: "memory");
            } else {
                asm volatile("cp.async.wait_group 0;" ::: "memory");
            }

            if (s < 16) {
                // pair-local visibility: both warps of pair wx have waited
                // on their own quarter-half; bar orders the smem writes.
                PAIR_BAR(1 + wx);
            } else if (s == 16) {
                __syncthreads();   // (a) all layer2 reads done + W3hi quarters visible
                // epilogue: acc -> h2 bf16 hi/lo planes (overwrite A planes)
#pragma unroll
                for (int mt = 0; mt < 2; ++mt) {
                    const int row0 = wy * 32 + mt * 16 + (lane >> 2);
#pragma unroll
                    for (int nt = 0; nt < 8; ++nt) {
                        const int e = wx * 64 + nt * 8 + (lane & 3) * 2;
                        float2 bv = *(const float2*)(b2g + p * 256 + e);
                        float v0 = fmaxf(acc[mt][nt][0] + bv.x, 0.f);
                        float v1 = fmaxf(acc[mt][nt][1] + bv.y, 0.f);
                        float v2 = fmaxf(acc[mt][nt][2] + bv.x, 0.f);
                        float v3 = fmaxf(acc[mt][nt][3] + bv.y, 0.f);
                        float h0 = __bfloat162float(__float2bfloat16(v0));
                        float h1 = __bfloat162float(__float2bfloat16(v1));
                        float h2 = __bfloat162float(__float2bfloat16(v2));
                        float h3 = __bfloat162float(__float2bfloat16(v3));
                        unsigned o0 = (unsigned)(row0 * 512 + e * 2) ^
                                      (unsigned)((row0 & 7) << 4);
                        unsigned o1 = (unsigned)((row0 + 8) * 512 + e * 2) ^
                                      (unsigned)(((row0 + 8) & 7) << 4);
                        *(unsigned*)(smc + OFF_AHI + o0) = pack_bf16x2(v0, v1);
                        *(unsigned*)(smc + OFF_ALO + o0) = pack_bf16x2(v0 - h0, v1 - h1);
                        *(unsigned*)(smc + OFF_AHI + o1) = pack_bf16x2(v2, v3);
                        *(unsigned*)(smc + OFF_ALO + o1) = pack_bf16x2(v2 - h2, v3 - h3);
                    }
                }
                __syncthreads();   // (b) h2 planes visible CTA-wide
            } else {
                __syncthreads();   // (c) W3lo quarters visible CTA-wide
            }

            const unsigned slot = ring + (unsigned)((g % 3) * 16384);

            if (s < 16) {
                // ---------------- layer2 stage: k-window s>>1 ----------
                const unsigned cw = (unsigned)((s >> 1) * 64);
                if ((s & 1) == 0) {
#pragma unroll
                    for (int ks2 = 0; ks2 < 2; ++ks2) {
                        const unsigned cc = cw + ks2 * 32;
                        unsigned ah[2][4], al[2][4], bb[4][4];
                        LDSM4(ah[0], sb + OFF_AHI + ((a_rb[0] + cc) ^ a_msk[0]));
                        LDSM4(ah[1], sb + OFF_AHI + ((a_rb[1] + cc) ^ a_msk[1]));
                        LDSM4(al[0], sb + OFF_ALO + ((a_rb[0] + cc) ^ a_msk[0]));
                        LDSM4(al[1], sb + OFF_ALO + ((a_rb[1] + cc) ^ a_msk[1]));
#pragma unroll
                        for (int t = 0; t < 4; ++t)
                            LDSM4(bb[t], slot + ((b_off[t] + ks2 * 32) ^ b_sw[t]));
#pragma unroll
                        for (int mt = 0; mt < 2; ++mt)
#pragma unroll
                            for (int t = 0; t < 4; ++t) {
                                MMA16816(acc[mt][2*t],   ah[mt], bb[t][0], bb[t][1]);
                                MMA16816(acc[mt][2*t+1], ah[mt], bb[t][2], bb[t][3]);
                                MMA16816(acc[mt][2*t],   al[mt], bb[t][0], bb[t][1]);
                                MMA16816(acc[mt][2*t+1], al[mt], bb[t][2], bb[t][3]);
                            }
                    }
                } else {
#pragma unroll
                    for (int ks2 = 0; ks2 < 2; ++ks2) {
                        const unsigned cc = cw + ks2 * 32;
                        unsigned ah[2][4], bb[4][4];
                        LDSM4(ah[0], sb + OFF_AHI + ((a_rb[0] + cc) ^ a_msk[0]));
                        LDSM4(ah[1], sb + OFF_AHI + ((a_rb[1] + cc) ^ a_msk[1]));
#pragma unroll
                        for (int t = 0; t < 4; ++t)
                            LDSM4(bb[t], slot + ((b_off[t] + ks2 * 32) ^ b_sw[t]));
#pragma unroll
                        for (int mt = 0; mt < 2; ++mt)
#pragma unroll
                            for (int t = 0; t < 4; ++t) {
                                MMA16816(acc[mt][2*t],   ah[mt], bb[t][0], bb[t][1]);
                                MMA16816(acc[mt][2*t+1], ah[mt], bb[t][2], bb[t][3]);
                            }
                    }
                }
            } else {
                // ---------------- layer3 stage (16=W3hi, 17=W3lo) ------
                const bool hi3 = (s == 16);
#pragma unroll
                for (int ks = 0; ks < 16; ++ks) {
                    const unsigned cc = (unsigned)(ks * 32);
                    unsigned ah[4], al[4], bb[4];
                    LDSM4(ah, sb + OFF_AHI + ((a3_rb + cc) ^ a3_msk));
                    if (hi3) LDSM4(al, sb + OFF_ALO + ((a3_rb + cc) ^ a3_msk));
                    LDSM4(bb, slot + (unsigned)((ks >> 1) * 2048) +
                              ((b3_off + (ks & 1) * 32) ^ b3_sw));
                    MMA16816(acc3[0], ah, bb[0], bb[1]);
                    MMA16816(acc3[1], ah, bb[2], bb[3]);
                    if (hi3) {
                        MMA16816(acc3[0], al, bb[0], bb[1]);
                        MMA16816(acc3[1], al, bb[2], bb[3]);
                    }
                }
            }
        }

        // ---------------- extraction: mask, sigmoid, accumulate --------
        {
            const float fl0 = (tflag[(n0 + r0) * PPARTS + p] != 0) ? 1.f : 0.f;
            const float fl1 = (tflag[(n0 + r1) * PPARTS + p] != 0) ? 1.f : 0.f;
#pragma unroll
            for (int t = 0; t < 2; ++t) {
                const int c = cbase + t * 8;
                const float b3a = g_b3[p * 32 + c];
                const float b3b = g_b3[p * 32 + c + 1];
                float v0 = acc3[t][0] + b3a, v1 = acc3[t][1] + b3b;
                float v2 = acc3[t][2] + b3a, v3 = acc3[t][3] + b3b;
                if (c == 20) {
                    v0 = (1.f / (1.f + __expf(-v0))) * fl0;
                    v2 = (1.f / (1.f + __expf(-v2))) * fl1;
                    out[(size_t)(n0 + r0) * OUTC + 21 + p] = v0;   // tocc
                    out[(size_t)(n0 + r1) * OUTC + 21 + p] = v2;
                } else {
                    v0 *= fl0; v2 *= fl1;
                }
                v1 *= fl0; v3 *= fl1;
                sums[t][0] += v0; sums[t][1] += v1;
                sums[t][2] += v2; sums[t][3] += v3;
            }
        }
        __syncthreads();   // (d) all layer3 smem reads done before next layer1
    }

    // ---------------- final masked means ----------------
    const float inv6 = 1.f / 6.f;
#pragma unroll
    for (int t = 0; t < 2; ++t) {
        const int c = cbase + t * 8;
        if (c < 21) {
            out[(size_t)(n0 + r0) * OUTC + c] = sums[t][0] * inv6;
            out[(size_t)(n0 + r1) * OUTC + c] = sums[t][2] * inv6;
        }
        if (c + 1 < 21) {
            out[(size_t)(n0 + r0) * OUTC + c + 1] = sums[t][1] * inv6;
            out[(size_t)(n0 + r1) * OUTC + c + 1] = sums[t][3] * inv6;
        }
    }
}

// ---------------------------------------------------------------------------
// launch
// ---------------------------------------------------------------------------
extern "C" void kernel_launch(void* const* d_in, const int* in_sizes, int n_in,
                              void* d_out, int out_size) {
    const float* tpts    = (const float*)d_in[0];
    const float* bigpts  = (const float*)d_in[1];
    const float* viewdir = (const float*)d_in[2];
    // d_in[3]=dists, d_in[4]=part_dist unused
    const float* frame   = (const float*)d_in[5];
    const float* W1      = (const float*)d_in[6];
    const float* b1      = (const float*)d_in[7];
    const float* W2      = (const float*)d_in[8];
    const float* b2      = (const float*)d_in[9];
    const float* W3      = (const float*)d_in[10];
    const float* b3      = (const float*)d_in[11];
    const float* Wocc    = (const float*)d_in[12];
    const float* bocc    = (const float*)d_in[13];
    const int*   tflag   = (const int*)d_in[14];
    float* out = (float*)d_out;

    prep_small<<<PPARTS, 256>>>(W1, b1, b3, bocc, frame);
    prep_B2<<<dim3(PPARTS, 256), 256>>>(W2);
    prep_B3<<<dim3(PPARTS, 256), 32>>>(W3, Wocc);

    cudaFuncSetAttribute(fused_kernel,
                         cudaFuncAttributeMaxDynamicSharedMemorySize,
                         SMEM_BYTES);
    fused_kernel<<<NCTAS, THREADS, SMEM_BYTES>>>(tpts, bigpts, viewdir,
                                                 b2, tflag, out);
}

// round 10
// speedup vs baseline: 1.2404x; 1.2404x over previous
#include <cuda_runtime.h>
#include <cuda_fp16.h>

// ---------------------------------------------------------------------------
// TPoseHuman fused 6-part MLP — layers 2 AND 3 on mma.sync **fp16** with
// error-compensated splits:
//   layer2: 2-chain (Ahi x Bhi + Ahi x Blo), dropped Alo term = 2^-12 rel
//   layer3: 3-chain (error ~2^-24), cost negligible
// R10 = R8 structure (3-slot cp.async ring, one CTA barrier per stage) with
// 33% fewer layer2 MMAs and no A-lo plane in layer2.
// ---------------------------------------------------------------------------

#define NPTS    65536
#define PPARTS  6
#define TM      64
#define NCTAS   (NPTS / TM)       // 1024
#define THREADS 256
#define OUTC    27
#define SPP     18                // stages per part: 16 layer2 + 2 layer3
#define NSTG    (PPARTS * SPP)    // 108

// ---- smem byte offsets ----
#define OFF_RING 0u               // 3 x 16384 = 49152
#define OFF_AHI  49152u           // 64 rows x 512B (A hi / h2 hi)
#define OFF_ALO  81920u           // 64 rows x 512B (h2 lo, layer3 only)
#define SMEM_BYTES 114688         // 112 KB -> 2 CTAs/SM

// ---------------------------------------------------------------------------
// asm helpers (baseline PTX, sm_80-era: family-safe on compute_103)
// ---------------------------------------------------------------------------
__device__ __forceinline__ unsigned smem_to_u32(const void* p) {
    unsigned a;
    asm("{ .reg .u64 t; cvta.to.shared.u64 t, %1; cvt.u32.u64 %0, t; }"
        : "=r"(a) : "l"(p));
    return a;
}
#define LDSM4(r, addr) \
    asm volatile("ldmatrix.sync.aligned.m8n8.x4.shared.b16 {%0,%1,%2,%3}, [%4];" \
        : "=r"((r)[0]), "=r"((r)[1]), "=r"((r)[2]), "=r"((r)[3]) : "r"(addr))
#define MMA16816(d, a, b0r, b1r) \
    asm volatile("mma.sync.aligned.m16n8k16.row.col.f32.f16.f16.f32 " \
        "{%0,%1,%2,%3}, {%4,%5,%6,%7}, {%8,%9}, {%0,%1,%2,%3};" \
        : "+f"((d)[0]), "+f"((d)[1]), "+f"((d)[2]), "+f"((d)[3]) \
        : "r"((a)[0]), "r"((a)[1]), "r"((a)[2]), "r"((a)[3]), \
          "r"(b0r), "r"(b1r))
__device__ __forceinline__ unsigned pack_h2(float x, float y) {
    __half2 t = __floats2half2_rn(x, y);
    return *(unsigned*)&t;
}

// ---------------------------------------------------------------------------
// persistent scratch
// ---------------------------------------------------------------------------
// Uniform 16KB stages: per part, stages 0..15 = W2^T k-chunks (hi,lo pairs),
// stages 16,17 = W3img (hi,lo). 64B-row layout, swizzle off ^= ((n>>1)&3)<<4.
__device__ __align__(16) unsigned char g_Bimg[NSTG * 16384];
__device__ __align__(16) float g_W1r  [PPARTS * 9 * 256];
__device__ __align__(16) float g_b1eff[PPARTS * 256];
__device__ __align__(16) float g_b3   [PPARTS * 32];

// ---------------------------------------------------------------------------
// prep kernels
// ---------------------------------------------------------------------------
__global__ void prep_small(const float* __restrict__ W1, const float* __restrict__ b1,
                           const float* __restrict__ b3, const float* __restrict__ bocc,
                           const float* __restrict__ frame) {
    int p = blockIdx.x, d = threadIdx.x;
    const int rows[9] = {0, 1, 2, 11, 12, 13, 14, 15, 16};
    float be = b1[p * 256 + d];
#pragma unroll
    for (int f = 0; f < 8; ++f)
        be += frame[f] * W1[(p * 17 + 3 + f) * 256 + d];
    g_b1eff[p * 256 + d] = be;
#pragma unroll
    for (int i = 0; i < 9; ++i)
        g_W1r[(p * 9 + i) * 256 + d] = W1[(p * 17 + rows[i]) * 256 + d];
    if (d < 32) {
        float v = 0.f;
        if (d < 20)  v = b3[p * 20 + d];
        if (d == 20) v = bocc[p];
        g_b3[p * 32 + d] = v;
    }
}

// layer2 B images: Bs[n][k] = W2[p][k][n], hi/lo fp16, 64B-row swizzled stages
__global__ void prep_B2(const float* __restrict__ W2) {
    int p = blockIdx.x, k = blockIdx.y, n = threadIdx.x;
    float w = W2[((size_t)(p * 256 + k)) * 256 + n];
    __half hi = __float2half_rn(w);
    __half lo = __float2half_rn(w - __half2float(hi));
    int s_hi = (k >> 5) * 2;                       // stage pair for this k-window
    unsigned off = (unsigned)(n * 64 + ((k >> 4) & 1) * 32 + (k & 15) * 2);
    off ^= (unsigned)(((n >> 1) & 3) << 4);
    unsigned char* base = g_Bimg + ((size_t)(p * SPP + s_hi)) * 16384;
    *(__half*)(base + off)         = hi;
    *(__half*)(base + 16384 + off) = lo;
}

// layer3 B images: B3[n][k] = [W3|Wocc|0pad]^T, n 0..31, k 0..255
__global__ void prep_B3(const float* __restrict__ W3,
                        const float* __restrict__ Wocc) {
    int p = blockIdx.x, k = blockIdx.y, n = threadIdx.x;   // n < 32
    float w = 0.f;
    if (n < 20)  w = W3[((size_t)(p * 256 + k)) * 20 + n];
    if (n == 20) w = Wocc[p * 256 + k];
    __half hi = __float2half_rn(w);
    __half lo = __float2half_rn(w - __half2float(hi));
    unsigned off = (unsigned)((k >> 5) * 2048 + n * 64 +
                              ((k >> 4) & 1) * 32 + (k & 15) * 2);
    off ^= (unsigned)(((n >> 1) & 3) << 4);
    unsigned char* base = g_Bimg + ((size_t)(p * SPP + 16)) * 16384;
    *(__half*)(base + off)         = hi;
    *(__half*)(base + 16384 + off) = lo;
}

// ---------------------------------------------------------------------------
// main fused kernel
// ---------------------------------------------------------------------------
__device__ __forceinline__ void prefetch_stage(unsigned ring, int tid, int g) {
    const unsigned char* src = g_Bimg + (size_t)g * 16384 + tid * 16;
    unsigned dst = ring + (unsigned)((g % 3) * 16384 + tid * 16);
#pragma unroll
    for (int j = 0; j < 4; ++j)
        asm volatile("cp.async.cg.shared.global [%0], [%1], 16;"
                     :: "r"(dst + j * 4096), "l"(src + j * 4096));
    asm volatile("cp.async.commit_group;" ::: "memory");
}

__global__ void __launch_bounds__(THREADS, 2)
fused_kernel(const float* __restrict__ tpts,
             const float* __restrict__ bigpts,
             const float* __restrict__ viewdir,
             const float* __restrict__ b2g,
             const int* __restrict__ tflag,
             float* __restrict__ out) {
    extern __shared__ unsigned char smc[];
    const int tid  = threadIdx.x;
    const int lane = tid & 31;
    const int wid  = tid >> 5;
    const int wy   = wid >> 2;          // layer2: m tile of 32
    const int wx   = wid & 3;           // layer2: n tile of 64
    const int n0   = blockIdx.x * TM;

    const unsigned sb   = smem_to_u32(smc);
    const unsigned ring = sb + OFF_RING;

    // ---- layer2 ldmatrix bases (validated R6-R9) ----
    unsigned a_rb[2], a_msk[2];
#pragma unroll
    for (int mt = 0; mt < 2; ++mt) {
        int ml = wy * 32 + mt * 16 + (lane & 15);
        a_rb[mt]  = (unsigned)(ml * 512 + (lane >> 4) * 16);
        a_msk[mt] = (unsigned)((ml & 7) << 4);
    }
    unsigned b_off[4], b_sw[4];
#pragma unroll
    for (int t = 0; t < 4; ++t) {
        int n = wx * 64 + t * 16 + (lane & 7) + ((lane & 16) ? 8 : 0);
        b_off[t] = (unsigned)(n * 64 + ((lane & 8) ? 16 : 0));
        b_sw[t]  = (unsigned)(((n >> 1) & 3) << 4);
    }
    // ---- layer3 bases: warp w -> m-tile (w>>1), n-half (w&1) ----
    const int ml3 = (wid >> 1) * 16 + (lane & 15);
    const unsigned a3_rb  = (unsigned)(ml3 * 512 + (lane >> 4) * 16);
    const unsigned a3_msk = (unsigned)((ml3 & 7) << 4);
    const int n3 = (wid & 1) * 16 + (lane & 7) + ((lane & 16) ? 8 : 0);
    const unsigned b3_off = (unsigned)(n3 * 64 + ((lane & 8) ? 16 : 0));
    const unsigned b3_sw  = (unsigned)(((n3 >> 1) & 3) << 4);
    const int r0 = (wid >> 1) * 16 + (lane >> 2);
    const int r1 = r0 + 8;
    const int cbase = (wid & 1) * 16 + (lane & 3) * 2;

    float sums[2][4];
#pragma unroll
    for (int t = 0; t < 2; ++t)
#pragma unroll
        for (int q = 0; q < 4; ++q) sums[t][q] = 0.f;

    prefetch_stage(ring, tid, 0);

    for (int p = 0; p < PPARTS; ++p) {
        // ---------------- layer 1 (thread = (m, d-chunk of 64)) ----------
        // h1 in fp32, store only fp16-hi A plane (2-chain layer2 drops A-lo)
        {
            const int m1 = tid & 63;
            const int dc = tid >> 6;
            const int gi = (n0 + m1) * PPARTS + p;
            float x[9];
            x[0] = tpts[gi*3];    x[1] = tpts[gi*3+1];    x[2] = tpts[gi*3+2];
            x[3] = bigpts[gi*3];  x[4] = bigpts[gi*3+1];  x[5] = bigpts[gi*3+2];
            x[6] = viewdir[gi*3]; x[7] = viewdir[gi*3+1]; x[8] = viewdir[gi*3+2];
            const float* w1  = g_W1r + p * 2304;
            const float* b1e = g_b1eff + p * 256;
            const unsigned amask = (unsigned)((m1 & 7) << 4);
            const unsigned mrow  = (unsigned)(m1 * 512 + dc * 128);
#pragma unroll 4
            for (int gq = 0; gq < 16; ++gq) {
                const int d = dc * 64 + gq * 4;
                float4 a = *(const float4*)(b1e + d);
#pragma unroll
                for (int i = 0; i < 9; ++i) {
                    float4 w = *(const float4*)(w1 + i * 256 + d);
                    a.x += x[i]*w.x; a.y += x[i]*w.y;
                    a.z += x[i]*w.z; a.w += x[i]*w.w;
                }
                a.x = fmaxf(a.x, 0.f); a.y = fmaxf(a.y, 0.f);
                a.z = fmaxf(a.z, 0.f); a.w = fmaxf(a.w, 0.f);
                unsigned o0 = (mrow + gq * 8) ^ amask;
                unsigned o1 = (mrow + gq * 8 + 4) ^ amask;
                *(unsigned*)(smc + OFF_AHI + o0) = pack_h2(a.x, a.y);
                *(unsigned*)(smc + OFF_AHI + o1) = pack_h2(a.z, a.w);
            }
        }
        __syncthreads();   // A plane ready CTA-wide

        float acc[2][8][4];
#pragma unroll
        for (int mt = 0; mt < 2; ++mt)
#pragma unroll
            for (int nt = 0; nt < 8; ++nt)
#pragma unroll
                for (int q = 0; q < 4; ++q) acc[mt][nt][q] = 0.f;
        float acc3[2][4];
#pragma unroll
        for (int t = 0; t < 2; ++t)
#pragma unroll
            for (int q = 0; q < 4; ++q) acc3[t][q] = 0.f;

#pragma unroll 1
        for (int s = 0; s < SPP; ++s) {
            const int g = p * SPP + s;
            if (g + 1 < NSTG) {
                prefetch_stage(ring, tid, g + 1);
                asm volatile("cp.async.wait_group 1;" ::: "memory");
            } else {
                asm volatile("cp.async.wait_group 0;" ::: "memory");
            }
            __syncthreads();   // stage g visible; all warps done with stage g-1

            // -------- epilogue between layer2 and layer3 stages --------
            if (s == 16) {
                // h1 plane dead: overwrite with h2 fp16 hi + lo (layer3 3-chain)
#pragma unroll
                for (int mt = 0; mt < 2; ++mt) {
                    const int row0 = wy * 32 + mt * 16 + (lane >> 2);
#pragma unroll
                    for (int nt = 0; nt < 8; ++nt) {
                        const int e = wx * 64 + nt * 8 + (lane & 3) * 2;
                        float2 bv = *(const float2*)(b2g + p * 256 + e);
                        float v0 = fmaxf(acc[mt][nt][0] + bv.x, 0.f);
                        float v1 = fmaxf(acc[mt][nt][1] + bv.y, 0.f);
                        float v2 = fmaxf(acc[mt][nt][2] + bv.x, 0.f);
                        float v3 = fmaxf(acc[mt][nt][3] + bv.y, 0.f);
                        float h0 = __half2float(__float2half_rn(v0));
                        float h1 = __half2float(__float2half_rn(v1));
                        float h2 = __half2float(__float2half_rn(v2));
                        float h3 = __half2float(__float2half_rn(v3));
                        unsigned o0 = (unsigned)(row0 * 512 + e * 2) ^
                                      (unsigned)((row0 & 7) << 4);
                        unsigned o1 = (unsigned)((row0 + 8) * 512 + e * 2) ^
                                      (unsigned)(((row0 + 8) & 7) << 4);
                        *(unsigned*)(smc + OFF_AHI + o0) = pack_h2(v0, v1);
                        *(unsigned*)(smc + OFF_ALO + o0) = pack_h2(v0 - h0, v1 - h1);
                        *(unsigned*)(smc + OFF_AHI + o1) = pack_h2(v2, v3);
                        *(unsigned*)(smc + OFF_ALO + o1) = pack_h2(v2 - h2, v3 - h3);
                    }
                }
                __syncthreads();   // h2 planes visible to all warps
            }

            const unsigned slot = ring + (unsigned)((g % 3) * 16384);

            if (s < 16) {
                // ------- layer2 stage: k-window s>>1, chain = (s&1) ------
                // 2-chain fp16: both hi and lo B stages consume the SAME
                // A-hi fragments -> identical body.
                const unsigned cw = (unsigned)((s >> 1) * 64);
#pragma unroll
                for (int ks2 = 0; ks2 < 2; ++ks2) {
                    const unsigned cc = cw + ks2 * 32;
                    unsigned ah[2][4], bb[4][4];
                    LDSM4(ah[0], sb + OFF_AHI + ((a_rb[0] + cc) ^ a_msk[0]));
                    LDSM4(ah[1], sb + OFF_AHI + ((a_rb[1] + cc) ^ a_msk[1]));
#pragma unroll
                    for (int t = 0; t < 4; ++t)
                        LDSM4(bb[t], slot + ((b_off[t] + ks2 * 32) ^ b_sw[t]));
#pragma unroll
                    for (int mt = 0; mt < 2; ++mt)
#pragma unroll
                        for (int t = 0; t < 4; ++t) {
                            MMA16816(acc[mt][2*t],   ah[mt], bb[t][0], bb[t][1]);
                            MMA16816(acc[mt][2*t+1], ah[mt], bb[t][2], bb[t][3]);
                        }
                }
            } else {
                // ------- layer3 stage (16=W3hi: 3-chain part, 17=W3lo) ---
                const bool hi3 = (s == 16);
#pragma unroll
                for (int ks = 0; ks < 16; ++ks) {
                    const unsigned cc = (unsigned)(ks * 32);
                    unsigned ah[4], al[4], bb[4];
                    LDSM4(ah, sb + OFF_AHI + ((a3_rb + cc) ^ a3_msk));
                    if (hi3) LDSM4(al, sb + OFF_ALO + ((a3_rb + cc) ^ a3_msk));
                    LDSM4(bb, slot + (unsigned)((ks >> 1) * 2048) +
                              ((b3_off + (ks & 1) * 32) ^ b3_sw));
                    MMA16816(acc3[0], ah, bb[0], bb[1]);
                    MMA16816(acc3[1], ah, bb[2], bb[3]);
                    if (hi3) {
                        MMA16816(acc3[0], al, bb[0], bb[1]);
                        MMA16816(acc3[1], al, bb[2], bb[3]);
                    }
                }
            }
            // 3-slot ring: next prefetch is race-free without trailing sync
        }

        // ---------------- extraction: mask, sigmoid, accumulate --------
        {
            const float fl0 = (tflag[(n0 + r0) * PPARTS + p] != 0) ? 1.f : 0.f;
            const float fl1 = (tflag[(n0 + r1) * PPARTS + p] != 0) ? 1.f : 0.f;
#pragma unroll
            for (int t = 0; t < 2; ++t) {
                const int c = cbase + t * 8;
                const float b3a = g_b3[p * 32 + c];
                const float b3b = g_b3[p * 32 + c + 1];
                float v0 = acc3[t][0] + b3a, v1 = acc3[t][1] + b3b;
                float v2 = acc3[t][2] + b3a, v3 = acc3[t][3] + b3b;
                if (c == 20) {
                    v0 = (1.f / (1.f + __expf(-v0))) * fl0;
                    v2 = (1.f / (1.f + __expf(-v2))) * fl1;
                    out[(size_t)(n0 + r0) * OUTC + 21 + p] = v0;   // tocc
                    out[(size_t)(n0 + r1) * OUTC + 21 + p] = v2;
                } else {
                    v0 *= fl0; v2 *= fl1;
                }
                v1 *= fl0; v3 *= fl1;
                sums[t][0] += v0; sums[t][1] += v1;
                sums[t][2] += v2; sums[t][3] += v3;
            }
        }
        __syncthreads();   // all warps past stage-17 MMAs before next layer1
    }

    // ---------------- final masked means ----------------
    const float inv6 = 1.f / 6.f;
#pragma unroll
    for (int t = 0; t < 2; ++t) {
        const int c = cbase + t * 8;
        if (c < 21) {
            out[(size_t)(n0 + r0) * OUTC + c] = sums[t][0] * inv6;
            out[(size_t)(n0 + r1) * OUTC + c] = sums[t][2] * inv6;
        }
        if (c + 1 < 21) {
            out[(size_t)(n0 + r0) * OUTC + c + 1] = sums[t][1] * inv6;
            out[(size_t)(n0 + r1) * OUTC + c + 1] = sums[t][3] * inv6;
        }
    }
}

// ---------------------------------------------------------------------------
// launch
// ---------------------------------------------------------------------------
extern "C" void kernel_launch(void* const* d_in, const int* in_sizes, int n_in,
                              void* d_out, int out_size) {
    const float* tpts    = (const float*)d_in[0];
    const float* bigpts  = (const float*)d_in[1];
    const float* viewdir = (const float*)d_in[2];
    // d_in[3]=dists, d_in[4]=part_dist unused
    const float* frame   = (const float*)d_in[5];
    const float* W1      = (const float*)d_in[6];
    const float* b1      = (const float*)d_in[7];
    const float* W2      = (const float*)d_in[8];
    const float* b2      = (const float*)d_in[9];
    const float* W3      = (const float*)d_in[10];
    const float* b3      = (const float*)d_in[11];
    const float* Wocc    = (const float*)d_in[12];
    const float* bocc    = (const float*)d_in[13];
    const int*   tflag   = (const int*)d_in[14];
    float* out = (float*)d_out;

    prep_small<<<PPARTS, 256>>>(W1, b1, b3, bocc, frame);
    prep_B2<<<dim3(PPARTS, 256), 256>>>(W2);
    prep_B3<<<dim3(PPARTS, 256), 32>>>(W3, Wocc);

    cudaFuncSetAttribute(fused_kernel,
                         cudaFuncAttributeMaxDynamicSharedMemorySize,
                         SMEM_BYTES);
    fused_kernel<<<NCTAS, THREADS, SMEM_BYTES>>>(tpts, bigpts, viewdir,
                                                 b2, tflag, out);
}

// round 11
// speedup vs baseline: 1.6318x; 1.3156x over previous
#include <cuda_runtime.h>
#include <cuda_fp16.h>

// ---------------------------------------------------------------------------
// TPoseHuman fused 6-part MLP — layers 2 AND 3 on mma.sync fp16.
//   layer2: SINGLE-chain fp16 (Ahi x Bhi). Two dropped cross terms, each
//           measured at ~1.2e-4 rel (R10) -> predicted total ~2.5e-4 << 1e-3.
//   layer3: 3-chain hi/lo (error ~2^-24), cost negligible.
// R11 = R10 structure (3-slot cp.async ring, one CTA barrier per stage),
// 10 stages/part (8 layer2 + 2 layer3) instead of 18.
// ---------------------------------------------------------------------------

#define NPTS    65536
#define PPARTS  6
#define TM      64
#define NCTAS   (NPTS / TM)       // 1024
#define THREADS 256
#define OUTC    27
#define SPP     10                // stages per part: 8 layer2 + 2 layer3
#define NSTG    (PPARTS * SPP)    // 60

// ---- smem byte offsets ----
#define OFF_RING 0u               // 3 x 16384 = 49152
#define OFF_AHI  49152u           // 64 rows x 512B (A hi / h2 hi)
#define OFF_ALO  81920u           // 64 rows x 512B (h2 lo, layer3 only)
#define SMEM_BYTES 114688         // 112 KB -> 2 CTAs/SM

// ---------------------------------------------------------------------------
// asm helpers (baseline PTX, sm_80-era: family-safe on compute_103)
// ---------------------------------------------------------------------------
__device__ __forceinline__ unsigned smem_to_u32(const void* p) {
    unsigned a;
    asm("{ .reg .u64 t; cvta.to.shared.u64 t, %1; cvt.u32.u64 %0, t; }"
        : "=r"(a) : "l"(p));
    return a;
}
#define LDSM4(r, addr) \
    asm volatile("ldmatrix.sync.aligned.m8n8.x4.shared.b16 {%0,%1,%2,%3}, [%4];" \
        : "=r"((r)[0]), "=r"((r)[1]), "=r"((r)[2]), "=r"((r)[3]) : "r"(addr))
#define MMA16816(d, a, b0r, b1r) \
    asm volatile("mma.sync.aligned.m16n8k16.row.col.f32.f16.f16.f32 " \
        "{%0,%1,%2,%3}, {%4,%5,%6,%7}, {%8,%9}, {%0,%1,%2,%3};" \
        : "+f"((d)[0]), "+f"((d)[1]), "+f"((d)[2]), "+f"((d)[3]) \
        : "r"((a)[0]), "r"((a)[1]), "r"((a)[2]), "r"((a)[3]), \
          "r"(b0r), "r"(b1r))
__device__ __forceinline__ unsigned pack_h2(float x, float y) {
    __half2 t = __floats2half2_rn(x, y);
    return *(unsigned*)&t;
}

// ---------------------------------------------------------------------------
// persistent scratch
// ---------------------------------------------------------------------------
// Uniform 16KB stages: per part, stages 0..7 = W2^T fp16 k-windows,
// stages 8,9 = W3img hi/lo. 64B-row layout, swizzle off ^= ((n>>1)&3)<<4.
__device__ __align__(16) unsigned char g_Bimg[NSTG * 16384];
__device__ __align__(16) float g_W1r  [PPARTS * 9 * 256];
__device__ __align__(16) float g_b1eff[PPARTS * 256];
__device__ __align__(16) float g_b3   [PPARTS * 32];

// ---------------------------------------------------------------------------
// prep kernels
// ---------------------------------------------------------------------------
__global__ void prep_small(const float* __restrict__ W1, const float* __restrict__ b1,
                           const float* __restrict__ b3, const float* __restrict__ bocc,
                           const float* __restrict__ frame) {
    int p = blockIdx.x, d = threadIdx.x;
    const int rows[9] = {0, 1, 2, 11, 12, 13, 14, 15, 16};
    float be = b1[p * 256 + d];
#pragma unroll
    for (int f = 0; f < 8; ++f)
        be += frame[f] * W1[(p * 17 + 3 + f) * 256 + d];
    g_b1eff[p * 256 + d] = be;
#pragma unroll
    for (int i = 0; i < 9; ++i)
        g_W1r[(p * 9 + i) * 256 + d] = W1[(p * 17 + rows[i]) * 256 + d];
    if (d < 32) {
        float v = 0.f;
        if (d < 20)  v = b3[p * 20 + d];
        if (d == 20) v = bocc[p];
        g_b3[p * 32 + d] = v;
    }
}

// layer2 B images: Bs[n][k] = W2[p][k][n], fp16, 64B-row swizzled stages
__global__ void prep_B2(const float* __restrict__ W2) {
    int p = blockIdx.x, k = blockIdx.y, n = threadIdx.x;
    float w = W2[((size_t)(p * 256 + k)) * 256 + n];
    __half hi = __float2half_rn(w);
    int stg = k >> 5;                              // k-window stage
    unsigned off = (unsigned)(n * 64 + ((k >> 4) & 1) * 32 + (k & 15) * 2);
    off ^= (unsigned)(((n >> 1) & 3) << 4);
    unsigned char* base = g_Bimg + ((size_t)(p * SPP + stg)) * 16384;
    *(__half*)(base + off) = hi;
}

// layer3 B images: B3[n][k] = [W3|Wocc|0pad]^T, n 0..31, k 0..255, hi/lo
__global__ void prep_B3(const float* __restrict__ W3,
                        const float* __restrict__ Wocc) {
    int p = blockIdx.x, k = blockIdx.y, n = threadIdx.x;   // n < 32
    float w = 0.f;
    if (n < 20)  w = W3[((size_t)(p * 256 + k)) * 20 + n];
    if (n == 20) w = Wocc[p * 256 + k];
    __half hi = __float2half_rn(w);
    __half lo = __float2half_rn(w - __half2float(hi));
    unsigned off = (unsigned)((k >> 5) * 2048 + n * 64 +
                              ((k >> 4) & 1) * 32 + (k & 15) * 2);
    off ^= (unsigned)(((n >> 1) & 3) << 4);
    unsigned char* base = g_Bimg + ((size_t)(p * SPP + 8)) * 16384;
    *(__half*)(base + off)         = hi;
    *(__half*)(base + 16384 + off) = lo;
}

// ---------------------------------------------------------------------------
// main fused kernel
// ---------------------------------------------------------------------------
__device__ __forceinline__ void prefetch_stage(unsigned ring, int tid, int g) {
    const unsigned char* src = g_Bimg + (size_t)g * 16384 + tid * 16;
    unsigned dst = ring + (unsigned)((g % 3) * 16384 + tid * 16);
#pragma unroll
    for (int j = 0; j < 4; ++j)
        asm volatile("cp.async.cg.shared.global [%0], [%1], 16;"
                     :: "r"(dst + j * 4096), "l"(src + j * 4096));
    asm volatile("cp.async.commit_group;" ::: "memory");
}

__global__ void __launch_bounds__(THREADS, 2)
fused_kernel(const float* __restrict__ tpts,
             const float* __restrict__ bigpts,
             const float* __restrict__ viewdir,
             const float* __restrict__ b2g,
             const int* __restrict__ tflag,
             float* __restrict__ out) {
    extern __shared__ unsigned char smc[];
    const int tid  = threadIdx.x;
    const int lane = tid & 31;
    const int wid  = tid >> 5;
    const int wy   = wid >> 2;          // layer2: m tile of 32
    const int wx   = wid & 3;           // layer2: n tile of 64
    const int n0   = blockIdx.x * TM;

    const unsigned sb   = smem_to_u32(smc);
    const unsigned ring = sb + OFF_RING;

    // ---- layer2 ldmatrix bases (validated R6-R10) ----
    unsigned a_rb[2], a_msk[2];
#pragma unroll
    for (int mt = 0; mt < 2; ++mt) {
        int ml = wy * 32 + mt * 16 + (lane & 15);
        a_rb[mt]  = (unsigned)(ml * 512 + (lane >> 4) * 16);
        a_msk[mt] = (unsigned)((ml & 7) << 4);
    }
    unsigned b_off[4], b_sw[4];
#pragma unroll
    for (int t = 0; t < 4; ++t) {
        int n = wx * 64 + t * 16 + (lane & 7) + ((lane & 16) ? 8 : 0);
        b_off[t] = (unsigned)(n * 64 + ((lane & 8) ? 16 : 0));
        b_sw[t]  = (unsigned)(((n >> 1) & 3) << 4);
    }
    // ---- layer3 bases: warp w -> m-tile (w>>1), n-half (w&1) ----
    const int ml3 = (wid >> 1) * 16 + (lane & 15);
    const unsigned a3_rb  = (unsigned)(ml3 * 512 + (lane >> 4) * 16);
    const unsigned a3_msk = (unsigned)((ml3 & 7) << 4);
    const int n3 = (wid & 1) * 16 + (lane & 7) + ((lane & 16) ? 8 : 0);
    const unsigned b3_off = (unsigned)(n3 * 64 + ((lane & 8) ? 16 : 0));
    const unsigned b3_sw  = (unsigned)(((n3 >> 1) & 3) << 4);
    const int r0 = (wid >> 1) * 16 + (lane >> 2);
    const int r1 = r0 + 8;
    const int cbase = (wid & 1) * 16 + (lane & 3) * 2;

    float sums[2][4];
#pragma unroll
    for (int t = 0; t < 2; ++t)
#pragma unroll
        for (int q = 0; q < 4; ++q) sums[t][q] = 0.f;

    prefetch_stage(ring, tid, 0);

    for (int p = 0; p < PPARTS; ++p) {
        // ---------------- layer 1 (thread = (m, d-chunk of 64)) ----------
        {
            const int m1 = tid & 63;
            const int dc = tid >> 6;
            const int gi = (n0 + m1) * PPARTS + p;
            float x[9];
            x[0] = tpts[gi*3];    x[1] = tpts[gi*3+1];    x[2] = tpts[gi*3+2];
            x[3] = bigpts[gi*3];  x[4] = bigpts[gi*3+1];  x[5] = bigpts[gi*3+2];
            x[6] = viewdir[gi*3]; x[7] = viewdir[gi*3+1]; x[8] = viewdir[gi*3+2];
            const float* w1  = g_W1r + p * 2304;
            const float* b1e = g_b1eff + p * 256;
            const unsigned amask = (unsigned)((m1 & 7) << 4);
            const unsigned mrow  = (unsigned)(m1 * 512 + dc * 128);
#pragma unroll 4
            for (int gq = 0; gq < 16; ++gq) {
                const int d = dc * 64 + gq * 4;
                float4 a = *(const float4*)(b1e + d);
#pragma unroll
                for (int i = 0; i < 9; ++i) {
                    float4 w = *(const float4*)(w1 + i * 256 + d);
                    a.x += x[i]*w.x; a.y += x[i]*w.y;
                    a.z += x[i]*w.z; a.w += x[i]*w.w;
                }
                a.x = fmaxf(a.x, 0.f); a.y = fmaxf(a.y, 0.f);
                a.z = fmaxf(a.z, 0.f); a.w = fmaxf(a.w, 0.f);
                unsigned o0 = (mrow + gq * 8) ^ amask;
                unsigned o1 = (mrow + gq * 8 + 4) ^ amask;
                *(unsigned*)(smc + OFF_AHI + o0) = pack_h2(a.x, a.y);
                *(unsigned*)(smc + OFF_AHI + o1) = pack_h2(a.z, a.w);
            }
        }
        __syncthreads();   // A plane ready CTA-wide

        float acc[2][8][4];
#pragma unroll
        for (int mt = 0; mt < 2; ++mt)
#pragma unroll
            for (int nt = 0; nt < 8; ++nt)
#pragma unroll
                for (int q = 0; q < 4; ++q) acc[mt][nt][q] = 0.f;
        float acc3[2][4];
#pragma unroll
        for (int t = 0; t < 2; ++t)
#pragma unroll
            for (int q = 0; q < 4; ++q) acc3[t][q] = 0.f;

#pragma unroll 1
        for (int s = 0; s < SPP; ++s) {
            const int g = p * SPP + s;
            if (g + 1 < NSTG) {
                prefetch_stage(ring, tid, g + 1);
                asm volatile("cp.async.wait_group 1;" ::: "memory");
            } else {
                asm volatile("cp.async.wait_group 0;" ::: "memory");
            }
            __syncthreads();   // stage g visible; all warps done with stage g-1

            // -------- epilogue between layer2 and layer3 stages --------
            if (s == 8) {
                // h1 plane dead: overwrite with h2 fp16 hi + lo (layer3 3-chain)
#pragma unroll
                for (int mt = 0; mt < 2; ++mt) {
                    const int row0 = wy * 32 + mt * 16 + (lane >> 2);
#pragma unroll
                    for (int nt = 0; nt < 8; ++nt) {
                        const int e = wx * 64 + nt * 8 + (lane & 3) * 2;
                        float2 bv = *(const float2*)(b2g + p * 256 + e);
                        float v0 = fmaxf(acc[mt][nt][0] + bv.x, 0.f);
                        float v1 = fmaxf(acc[mt][nt][1] + bv.y, 0.f);
                        float v2 = fmaxf(acc[mt][nt][2] + bv.x, 0.f);
                        float v3 = fmaxf(acc[mt][nt][3] + bv.y, 0.f);
                        float h0 = __half2float(__float2half_rn(v0));
                        float h1 = __half2float(__float2half_rn(v1));
                        float h2 = __half2float(__float2half_rn(v2));
                        float h3 = __half2float(__float2half_rn(v3));
                        unsigned o0 = (unsigned)(row0 * 512 + e * 2) ^
                                      (unsigned)((row0 & 7) << 4);
                        unsigned o1 = (unsigned)((row0 + 8) * 512 + e * 2) ^
                                      (unsigned)(((row0 + 8) & 7) << 4);
                        *(unsigned*)(smc + OFF_AHI + o0) = pack_h2(v0, v1);
                        *(unsigned*)(smc + OFF_ALO + o0) = pack_h2(v0 - h0, v1 - h1);
                        *(unsigned*)(smc + OFF_AHI + o1) = pack_h2(v2, v3);
                        *(unsigned*)(smc + OFF_ALO + o1) = pack_h2(v2 - h2, v3 - h3);
                    }
                }
                __syncthreads();   // h2 planes visible to all warps
            }

            const unsigned slot = ring + (unsigned)((g % 3) * 16384);

            if (s < 8) {
                // ------- layer2 stage: k-window s, single fp16 chain -----
                const unsigned cw = (unsigned)(s * 64);
#pragma unroll
                for (int ks2 = 0; ks2 < 2; ++ks2) {
                    const unsigned cc = cw + ks2 * 32;
                    unsigned ah[2][4], bb[4][4];
                    LDSM4(ah[0], sb + OFF_AHI + ((a_rb[0] + cc) ^ a_msk[0]));
                    LDSM4(ah[1], sb + OFF_AHI + ((a_rb[1] + cc) ^ a_msk[1]));
#pragma unroll
                    for (int t = 0; t < 4; ++t)
                        LDSM4(bb[t], slot + ((b_off[t] + ks2 * 32) ^ b_sw[t]));
#pragma unroll
                    for (int mt = 0; mt < 2; ++mt)
#pragma unroll
                        for (int t = 0; t < 4; ++t) {
                            MMA16816(acc[mt][2*t],   ah[mt], bb[t][0], bb[t][1]);
                            MMA16816(acc[mt][2*t+1], ah[mt], bb[t][2], bb[t][3]);
                        }
                }
            } else {
                // ------- layer3 stage (8=W3hi: 3-chain part, 9=W3lo) -----
                const bool hi3 = (s == 8);
#pragma unroll
                for (int ks = 0; ks < 16; ++ks) {
                    const unsigned cc = (unsigned)(ks * 32);
                    unsigned ah[4], al[4], bb[4];
                    LDSM4(ah, sb + OFF_AHI + ((a3_rb + cc) ^ a3_msk));
                    if (hi3) LDSM4(al, sb + OFF_ALO + ((a3_rb + cc) ^ a3_msk));
                    LDSM4(bb, slot + (unsigned)((ks >> 1) * 2048) +
                              ((b3_off + (ks & 1) * 32) ^ b3_sw));
                    MMA16816(acc3[0], ah, bb[0], bb[1]);
                    MMA16816(acc3[1], ah, bb[2], bb[3]);
                    if (hi3) {
                        MMA16816(acc3[0], al, bb[0], bb[1]);
                        MMA16816(acc3[1], al, bb[2], bb[3]);
                    }
                }
            }
            // 3-slot ring: next prefetch is race-free without trailing sync
        }

        // ---------------- extraction: mask, sigmoid, accumulate --------
        {
            const float fl0 = (tflag[(n0 + r0) * PPARTS + p] != 0) ? 1.f : 0.f;
            const float fl1 = (tflag[(n0 + r1) * PPARTS + p] != 0) ? 1.f : 0.f;
#pragma unroll
            for (int t = 0; t < 2; ++t) {
                const int c = cbase + t * 8;
                const float b3a = g_b3[p * 32 + c];
                const float b3b = g_b3[p * 32 + c + 1];
                float v0 = acc3[t][0] + b3a, v1 = acc3[t][1] + b3b;
                float v2 = acc3[t][2] + b3a, v3 = acc3[t][3] + b3b;
                if (c == 20) {
                    v0 = (1.f / (1.f + __expf(-v0))) * fl0;
                    v2 = (1.f / (1.f + __expf(-v2))) * fl1;
                    out[(size_t)(n0 + r0) * OUTC + 21 + p] = v0;   // tocc
                    out[(size_t)(n0 + r1) * OUTC + 21 + p] = v2;
                } else {
                    v0 *= fl0; v2 *= fl1;
                }
                v1 *= fl0; v3 *= fl1;
                sums[t][0] += v0; sums[t][1] += v1;
                sums[t][2] += v2; sums[t][3] += v3;
            }
        }
        __syncthreads();   // all warps past stage-9 MMAs before next layer1
    }

    // ---------------- final masked means ----------------
    const float inv6 = 1.f / 6.f;
#pragma unroll
    for (int t = 0; t < 2; ++t) {
        const int c = cbase + t * 8;
        if (c < 21) {
            out[(size_t)(n0 + r0) * OUTC + c] = sums[t][0] * inv6;
            out[(size_t)(n0 + r1) * OUTC + c] = sums[t][2] * inv6;
        }
        if (c + 1 < 21) {
            out[(size_t)(n0 + r0) * OUTC + c + 1] = sums[t][1] * inv6;
            out[(size_t)(n0 + r1) * OUTC + c + 1] = sums[t][3] * inv6;
        }
    }
}

// ---------------------------------------------------------------------------
// launch
// ---------------------------------------------------------------------------
extern "C" void kernel_launch(void* const* d_in, const int* in_sizes, int n_in,
                              void* d_out, int out_size) {
    const float* tpts    = (const float*)d_in[0];
    const float* bigpts  = (const float*)d_in[1];
    const float* viewdir = (const float*)d_in[2];
    // d_in[3]=dists, d_in[4]=part_dist unused
    const float* frame   = (const float*)d_in[5];
    const float* W1      = (const float*)d_in[6];
    const float* b1      = (const float*)d_in[7];
    const float* W2      = (const float*)d_in[8];
    const float* b2      = (const float*)d_in[9];
    const float* W3      = (const float*)d_in[10];
    const float* b3      = (const float*)d_in[11];
    const float* Wocc    = (const float*)d_in[12];
    const float* bocc    = (const float*)d_in[13];
    const int*   tflag   = (const int*)d_in[14];
    float* out = (float*)d_out;

    prep_small<<<PPARTS, 256>>>(W1, b1, b3, bocc, frame);
    prep_B2<<<dim3(PPARTS, 256), 256>>>(W2);
    prep_B3<<<dim3(PPARTS, 256), 32>>>(W3, Wocc);

    cudaFuncSetAttribute(fused_kernel,
                         cudaFuncAttributeMaxDynamicSharedMemorySize,
                         SMEM_BYTES);
    fused_kernel<<<NCTAS, THREADS, SMEM_BYTES>>>(tpts, bigpts, viewdir,
                                                 b2, tflag, out);
}